// round 1
// baseline (speedup 1.0000x reference)
#include <cuda_runtime.h>
#include <cuda_bf16.h>
#include <cstdint>

#define N_Q   4096
#define N_R   65536
#define DIM   512
#define K_TOP 16

// ---------------- scratch (static __device__, allocation-free) ----------------
__device__ __nv_bfloat16 g_xb[(size_t)N_Q * DIM];          // 4 MB
__device__ __nv_bfloat16 g_rb[(size_t)N_R * DIM];          // 64 MB
__device__ float         g_scores[(size_t)N_Q * N_R];      // 1 GB

// ---------------- helpers ----------------
__device__ __forceinline__ void cp_async16(uint32_t dst, const void* src) {
    asm volatile("cp.async.cg.shared.global [%0], [%1], 16;\n" :: "r"(dst), "l"(src));
}
__device__ __forceinline__ void cp_commit() {
    asm volatile("cp.async.commit_group;\n" ::: "memory");
}
__device__ __forceinline__ void cp_wait0() {
    asm volatile("cp.async.wait_group 0;\n" ::: "memory");
}
__device__ __forceinline__ void mma_bf16(float* c, const uint32_t* a, const uint32_t* b) {
    asm volatile(
        "mma.sync.aligned.m16n8k16.row.col.f32.bf16.bf16.f32 "
        "{%0,%1,%2,%3}, {%4,%5,%6,%7}, {%8,%9}, {%0,%1,%2,%3};\n"
        : "+f"(c[0]), "+f"(c[1]), "+f"(c[2]), "+f"(c[3])
        : "r"(a[0]), "r"(a[1]), "r"(a[2]), "r"(a[3]),
          "r"(b[0]), "r"(b[1]));
}

// ---------------- prep: normalize x (fp32) -> bf16 ----------------
__global__ void prep_x_kernel(const float* __restrict__ x) {
    int row = blockIdx.x;
    int t = threadIdx.x;  // 128 threads
    const float* xr = x + (size_t)row * DIM;
    float v[4];
    float ss = 0.f;
#pragma unroll
    for (int i = 0; i < 4; ++i) { v[i] = xr[i * 128 + t]; ss += v[i] * v[i]; }
#pragma unroll
    for (int o = 16; o > 0; o >>= 1) ss += __shfl_xor_sync(0xffffffffu, ss, o);
    __shared__ float red[4];
    if ((t & 31) == 0) red[t >> 5] = ss;
    __syncthreads();
    float tot = red[0] + red[1] + red[2] + red[3];
    float scale = 1.0f / fmaxf(sqrtf(tot), 1e-12f);
#pragma unroll
    for (int i = 0; i < 4; ++i)
        g_xb[(size_t)row * DIM + i * 128 + t] = __float2bfloat16(v[i] * scale);
}

// ---------------- prep: refs fp32 -> bf16 ----------------
__global__ void conv_refs_kernel(const float* __restrict__ r) {
    size_t total4 = (size_t)N_R * DIM / 4;
    const float4* r4 = (const float4*)r;
    __nv_bfloat162* out2 = (__nv_bfloat162*)g_rb;
    for (size_t i = (size_t)blockIdx.x * blockDim.x + threadIdx.x; i < total4;
         i += (size_t)gridDim.x * blockDim.x) {
        float4 f = r4[i];
        out2[i * 2]     = __floats2bfloat162_rn(f.x, f.y);
        out2[i * 2 + 1] = __floats2bfloat162_rn(f.z, f.w);
    }
}

// ---------------- GEMM: scores = xn @ refs^T (bf16 in, fp32 acc) ----------------
#define BM 128
#define BN 128
#define BK 32
#define PITCH 20  // uints per smem row (16 data + 4 pad) -> conflict-free frag reads

__global__ __launch_bounds__(256, 1) void gemm_kernel() {
    __shared__ uint32_t As[2][BM * PITCH];
    __shared__ uint32_t Bs[2][BN * PITCH];

    int tid = threadIdx.x;
    int m0 = blockIdx.x * BM;
    int n0 = blockIdx.y * BN;
    const __nv_bfloat16* Ag = g_xb + (size_t)m0 * DIM;
    const __nv_bfloat16* Bg = g_rb + (size_t)n0 * DIM;

    int lrow0 = tid >> 2;   // 0..63
    int lkc   = tid & 3;    // 16B chunk within row

    float acc[16][4];
#pragma unroll
    for (int i = 0; i < 16; ++i)
#pragma unroll
        for (int j = 0; j < 4; ++j) acc[i][j] = 0.f;

    int lane = tid & 31, warp = tid >> 5;
    int wm = (warp >> 2) * 64;   // 0 / 64
    int wn = (warp & 3) * 32;    // 0 / 32 / 64 / 96
    int g = lane >> 2, q = lane & 3;

    // prologue load stage 0
    {
#pragma unroll
        for (int h = 0; h < 2; ++h) {
            int row = lrow0 + h * 64;
            cp_async16((uint32_t)__cvta_generic_to_shared(&As[0][row * PITCH + lkc * 4]),
                       Ag + (size_t)row * DIM + lkc * 8);
            cp_async16((uint32_t)__cvta_generic_to_shared(&Bs[0][row * PITCH + lkc * 4]),
                       Bg + (size_t)row * DIM + lkc * 8);
        }
        cp_commit();
    }

    const int NKT = DIM / BK;  // 16
    for (int kt = 0; kt < NKT; ++kt) {
        cp_wait0();
        __syncthreads();
        if (kt + 1 < NKT) {
            int s = (kt + 1) & 1;
            int kbase = (kt + 1) * BK;
#pragma unroll
            for (int h = 0; h < 2; ++h) {
                int row = lrow0 + h * 64;
                cp_async16((uint32_t)__cvta_generic_to_shared(&As[s][row * PITCH + lkc * 4]),
                           Ag + (size_t)row * DIM + kbase + lkc * 8);
                cp_async16((uint32_t)__cvta_generic_to_shared(&Bs[s][row * PITCH + lkc * 4]),
                           Bg + (size_t)row * DIM + kbase + lkc * 8);
            }
            cp_commit();
        }
        int s = kt & 1;
#pragma unroll
        for (int kk = 0; kk < 2; ++kk) {
            uint32_t af[4][4], bf[4][2];
#pragma unroll
            for (int mf = 0; mf < 4; ++mf) {
                int r0 = wm + mf * 16 + g;
                af[mf][0] = As[s][r0 * PITCH + kk * 8 + q];
                af[mf][1] = As[s][(r0 + 8) * PITCH + kk * 8 + q];
                af[mf][2] = As[s][r0 * PITCH + kk * 8 + q + 4];
                af[mf][3] = As[s][(r0 + 8) * PITCH + kk * 8 + q + 4];
            }
#pragma unroll
            for (int nf = 0; nf < 4; ++nf) {
                int nr = wn + nf * 8 + g;
                bf[nf][0] = Bs[s][nr * PITCH + kk * 8 + q];
                bf[nf][1] = Bs[s][nr * PITCH + kk * 8 + q + 4];
            }
#pragma unroll
            for (int mf = 0; mf < 4; ++mf)
#pragma unroll
                for (int nf = 0; nf < 4; ++nf)
                    mma_bf16(acc[mf * 4 + nf], af[mf], bf[nf]);
        }
    }

    // epilogue: write scores
    float* Sg = g_scores + (size_t)m0 * N_R + n0;
#pragma unroll
    for (int mf = 0; mf < 4; ++mf) {
#pragma unroll
        for (int nf = 0; nf < 4; ++nf) {
            int r0 = wm + mf * 16 + g;
            int c0 = wn + nf * 8 + q * 2;
            float* p0 = Sg + (size_t)r0 * N_R + c0;
            float* p1 = Sg + (size_t)(r0 + 8) * N_R + c0;
            ((float2*)p0)[0] = make_float2(acc[mf * 4 + nf][0], acc[mf * 4 + nf][1]);
            ((float2*)p1)[0] = make_float2(acc[mf * 4 + nf][2], acc[mf * 4 + nf][3]);
        }
    }
}

// ---------------- top-k + weights ----------------
__global__ __launch_bounds__(256) void topk_kernel(float* __restrict__ out) {
    int qy = blockIdx.x;
    const float* row = g_scores + (size_t)qy * N_R;
    float t[K_TOP];
#pragma unroll
    for (int j = 0; j < K_TOP; ++j) t[j] = -1e30f;

    for (int i = threadIdx.x; i < N_R; i += 256) {
        float v = row[i];
        if (v > t[K_TOP - 1]) {
            t[K_TOP - 1] = v;
#pragma unroll
            for (int j = K_TOP - 1; j > 0; --j) {
                float a = t[j - 1], b = t[j];
                t[j - 1] = fmaxf(a, b);
                t[j]     = fminf(a, b);
            }
        }
    }

    __shared__ float sm[256 * K_TOP];
#pragma unroll
    for (int j = 0; j < K_TOP; ++j) sm[threadIdx.x * K_TOP + j] = t[j];
    __syncthreads();

    for (int half = 128; half >= 1; half >>= 1) {
        if (threadIdx.x < (unsigned)half) {
            float* a = &sm[threadIdx.x * K_TOP];
            float* b = &sm[(threadIdx.x + half) * K_TOP];
            float m[K_TOP];
            int ia = 0, ib = 0;
#pragma unroll
            for (int j = 0; j < K_TOP; ++j) {
                float av = a[ia], bv = b[ib];
                if (av >= bv) { m[j] = av; ++ia; }
                else          { m[j] = bv; ++ib; }
            }
#pragma unroll
            for (int j = 0; j < K_TOP; ++j) a[j] = m[j];
        }
        __syncthreads();
    }

    if (threadIdx.x == 0) {
        float w[K_TOP];
        float ssum = 0.f;
#pragma unroll
        for (int j = 0; j < K_TOP; ++j) {
            float s = sm[j];                       // descending dot -> ascending distance
            float d2 = fmaxf(2.0f - 2.0f * s, 1e-12f);
            float d = sqrtf(d2);
            w[j] = expf(-d);
            ssum += w[j];
        }
        float inv = 1.0f / fmaxf(ssum, 1e-12f);
#pragma unroll
        for (int j = 0; j < K_TOP; ++j)
            out[(size_t)qy * K_TOP + j] = w[j] * inv;
    }
}

// ---------------- launch ----------------
extern "C" void kernel_launch(void* const* d_in, const int* in_sizes, int n_in,
                              void* d_out, int out_size) {
    const float* x    = (const float*)d_in[0];
    const float* refs = (const float*)d_in[1];
    float* out = (float*)d_out;

    prep_x_kernel<<<N_Q, 128>>>(x);
    conv_refs_kernel<<<16384, 256>>>(refs);
    gemm_kernel<<<dim3(N_Q / BM, N_R / BN), 256>>>();
    topk_kernel<<<N_Q, 256>>>(out);
}

// round 2
// speedup vs baseline: 1.3705x; 1.3705x over previous
#include <cuda_runtime.h>
#include <cuda_bf16.h>
#include <cstdint>

#define N_Q    4096
#define N_R    65536
#define DIM    512
#define K_TOP  16

#define BM     128
#define BN     128
#define BK     32
#define PITCH  20            // uint32 per smem row (16 data + 4 pad)
#define SPITCH 130           // floats per scores row (128 + 2 pad)
#define NSPLIT 32
#define CHUNK  (N_R / NSPLIT)     // 2048
#define NT     (CHUNK / BN)       // 16

#define AS_OFF 0
#define BS_OFF (2 * BM * PITCH * 4)
#define SC_OFF (2 * BS_OFF)
#define SMEM_TOTAL (SC_OFF + BM * SPITCH * 4)   // 107,520 B

// ---------------- scratch ----------------
__device__ __nv_bfloat16 g_xb[(size_t)N_Q * DIM];            // 4 MB
__device__ __nv_bfloat16 g_rb[(size_t)N_R * DIM];            // 64 MB
__device__ float         g_cand[(size_t)N_Q * NSPLIT * K_TOP]; // 8 MB

// ---------------- helpers ----------------
__device__ __forceinline__ void cp_async16(uint32_t dst, const void* src) {
    asm volatile("cp.async.cg.shared.global [%0], [%1], 16;\n" :: "r"(dst), "l"(src));
}
__device__ __forceinline__ void cp_commit() {
    asm volatile("cp.async.commit_group;\n" ::: "memory");
}
__device__ __forceinline__ void cp_wait0() {
    asm volatile("cp.async.wait_group 0;\n" ::: "memory");
}
__device__ __forceinline__ void mma_bf16(float* c, const uint32_t* a, const uint32_t* b) {
    asm volatile(
        "mma.sync.aligned.m16n8k16.row.col.f32.bf16.bf16.f32 "
        "{%0,%1,%2,%3}, {%4,%5,%6,%7}, {%8,%9}, {%0,%1,%2,%3};\n"
        : "+f"(c[0]), "+f"(c[1]), "+f"(c[2]), "+f"(c[3])
        : "r"(a[0]), "r"(a[1]), "r"(a[2]), "r"(a[3]),
          "r"(b[0]), "r"(b[1]));
}

// ---------------- prep: normalize x -> bf16 ----------------
__global__ void prep_x_kernel(const float* __restrict__ x) {
    int row = blockIdx.x;
    int t = threadIdx.x;
    const float* xr = x + (size_t)row * DIM;
    float v[4];
    float ss = 0.f;
#pragma unroll
    for (int i = 0; i < 4; ++i) { v[i] = xr[i * 128 + t]; ss += v[i] * v[i]; }
#pragma unroll
    for (int o = 16; o > 0; o >>= 1) ss += __shfl_xor_sync(0xffffffffu, ss, o);
    __shared__ float red[4];
    if ((t & 31) == 0) red[t >> 5] = ss;
    __syncthreads();
    float tot = red[0] + red[1] + red[2] + red[3];
    float scale = 1.0f / fmaxf(sqrtf(tot), 1e-12f);
#pragma unroll
    for (int i = 0; i < 4; ++i)
        g_xb[(size_t)row * DIM + i * 128 + t] = __float2bfloat16(v[i] * scale);
}

// ---------------- prep: refs fp32 -> bf16 ----------------
__global__ void conv_refs_kernel(const float* __restrict__ r) {
    size_t total4 = (size_t)N_R * DIM / 4;
    const float4* r4 = (const float4*)r;
    __nv_bfloat162* out2 = (__nv_bfloat162*)g_rb;
    for (size_t i = (size_t)blockIdx.x * blockDim.x + threadIdx.x; i < total4;
         i += (size_t)gridDim.x * blockDim.x) {
        float4 f = r4[i];
        out2[i * 2]     = __floats2bfloat162_rn(f.x, f.y);
        out2[i * 2 + 1] = __floats2bfloat162_rn(f.z, f.w);
    }
}

// ---------------- fused GEMM + per-chunk top-16 ----------------
__global__ __launch_bounds__(256, 2) void fused_gemm_topk_kernel() {
    extern __shared__ uint8_t smem[];
    uint32_t* As = (uint32_t*)(smem + AS_OFF);    // [2][BM*PITCH]
    uint32_t* Bs = (uint32_t*)(smem + BS_OFF);    // [2][BN*PITCH]
    float*    sc = (float*)(smem + SC_OFF);       // [BM][SPITCH]

    int tid = threadIdx.x;
    int m0 = blockIdx.x * BM;
    int n0 = blockIdx.y * CHUNK;
    const __nv_bfloat16* Ag = g_xb + (size_t)m0 * DIM;

    int lrow0 = tid >> 2;   // 0..63
    int lkc   = tid & 3;

    int lane = tid & 31, warp = tid >> 5;
    int wm = (warp >> 2) * 64;
    int wn = (warp & 3) * 32;
    int g = lane >> 2, q = lane & 3;

    // per-thread top-16 (row = tid>>1, col-half = tid&1), sorted descending
    float t[K_TOP];
#pragma unroll
    for (int j = 0; j < K_TOP; ++j) t[j] = -1e30f;

    float acc[16][4];
#pragma unroll
    for (int i = 0; i < 16; ++i)
#pragma unroll
        for (int j = 0; j < 4; ++j) acc[i][j] = 0.f;

    // prologue: stage 0 of tile 0
    {
        const __nv_bfloat16* Bg = g_rb + (size_t)n0 * DIM;
#pragma unroll
        for (int h = 0; h < 2; ++h) {
            int row = lrow0 + h * 64;
            cp_async16((uint32_t)__cvta_generic_to_shared(&As[row * PITCH + lkc * 4]),
                       Ag + (size_t)row * DIM + lkc * 8);
            cp_async16((uint32_t)__cvta_generic_to_shared(&Bs[row * PITCH + lkc * 4]),
                       Bg + (size_t)row * DIM + lkc * 8);
        }
        cp_commit();
    }

    const int NKT = DIM / BK;   // 16
    for (int nt = 0; nt < NT; ++nt) {
        const __nv_bfloat16* Bg = g_rb + (size_t)(n0 + nt * BN) * DIM;

        for (int kt = 0; kt < NKT; ++kt) {
            cp_wait0();
            __syncthreads();

            // issue next loads: next kt of this tile, or kt=0 of next tile (overlaps scan)
            if (kt + 1 < NKT) {
                int s = (kt + 1) & 1;
                int kbase = (kt + 1) * BK;
#pragma unroll
                for (int h = 0; h < 2; ++h) {
                    int row = lrow0 + h * 64;
                    cp_async16((uint32_t)__cvta_generic_to_shared(&As[s * BM * PITCH + row * PITCH + lkc * 4]),
                               Ag + (size_t)row * DIM + kbase + lkc * 8);
                    cp_async16((uint32_t)__cvta_generic_to_shared(&Bs[s * BM * PITCH + row * PITCH + lkc * 4]),
                               Bg + (size_t)row * DIM + kbase + lkc * 8);
                }
                cp_commit();
            } else if (nt + 1 < NT) {
                const __nv_bfloat16* Bg2 = g_rb + (size_t)(n0 + (nt + 1) * BN) * DIM;
#pragma unroll
                for (int h = 0; h < 2; ++h) {
                    int row = lrow0 + h * 64;
                    cp_async16((uint32_t)__cvta_generic_to_shared(&As[row * PITCH + lkc * 4]),
                               Ag + (size_t)row * DIM + lkc * 8);
                    cp_async16((uint32_t)__cvta_generic_to_shared(&Bs[row * PITCH + lkc * 4]),
                               Bg2 + (size_t)row * DIM + lkc * 8);
                }
                cp_commit();
            }

            int s = kt & 1;
#pragma unroll
            for (int kk = 0; kk < 2; ++kk) {
                uint32_t af[4][4], bf[4][2];
#pragma unroll
                for (int mf = 0; mf < 4; ++mf) {
                    int r0 = wm + mf * 16 + g;
                    af[mf][0] = As[s * BM * PITCH + r0 * PITCH + kk * 8 + q];
                    af[mf][1] = As[s * BM * PITCH + (r0 + 8) * PITCH + kk * 8 + q];
                    af[mf][2] = As[s * BM * PITCH + r0 * PITCH + kk * 8 + q + 4];
                    af[mf][3] = As[s * BM * PITCH + (r0 + 8) * PITCH + kk * 8 + q + 4];
                }
#pragma unroll
                for (int nf = 0; nf < 4; ++nf) {
                    int nr = wn + nf * 8 + g;
                    bf[nf][0] = Bs[s * BM * PITCH + nr * PITCH + kk * 8 + q];
                    bf[nf][1] = Bs[s * BM * PITCH + nr * PITCH + kk * 8 + q + 4];
                }
#pragma unroll
                for (int mf = 0; mf < 4; ++mf)
#pragma unroll
                    for (int nf = 0; nf < 4; ++nf)
                        mma_bf16(acc[mf * 4 + nf], af[mf], bf[nf]);
            }
        }

        // epilogue: spill tile scores to smem
#pragma unroll
        for (int mf = 0; mf < 4; ++mf) {
#pragma unroll
            for (int nf = 0; nf < 4; ++nf) {
                int r0 = wm + mf * 16 + g;
                int c0 = wn + nf * 8 + q * 2;
                sc[r0 * SPITCH + c0]       = acc[mf * 4 + nf][0];
                sc[r0 * SPITCH + c0 + 1]   = acc[mf * 4 + nf][1];
                sc[(r0 + 8) * SPITCH + c0]     = acc[mf * 4 + nf][2];
                sc[(r0 + 8) * SPITCH + c0 + 1] = acc[mf * 4 + nf][3];
                acc[mf * 4 + nf][0] = 0.f; acc[mf * 4 + nf][1] = 0.f;
                acc[mf * 4 + nf][2] = 0.f; acc[mf * 4 + nf][3] = 0.f;
            }
        }
        __syncthreads();

        // top-k scan: thread owns (row tid>>1, cols (tid&1)*64 .. +63)
        {
            const float* rowp = sc + (tid >> 1) * SPITCH + (tid & 1) * 64;
            float th = t[K_TOP - 1];
#pragma unroll 8
            for (int j = 0; j < 64; ++j) {
                float v = rowp[j];
                if (v > th) {
                    t[K_TOP - 1] = v;
#pragma unroll
                    for (int p = K_TOP - 1; p > 0; --p) {
                        float a = t[p - 1], b = t[p];
                        t[p - 1] = fmaxf(a, b);
                        t[p]     = fminf(a, b);
                    }
                    th = t[K_TOP - 1];
                }
            }
        }
        __syncthreads();
    }

    // pair-merge: combine the two col-halves of each row, write candidates
    float* lists = sc;   // reuse: 256*16 floats
#pragma unroll
    for (int j = 0; j < K_TOP; ++j) lists[tid * K_TOP + j] = t[j];
    __syncthreads();

    if ((tid & 1) == 0) {
        const float* a = &lists[tid * K_TOP];
        const float* b = &lists[(tid + 1) * K_TOP];
        float m[K_TOP];
        int ia = 0, ib = 0;
#pragma unroll
        for (int j = 0; j < K_TOP; ++j) {
            float av = a[ia], bv = b[ib];
            if (av >= bv) { m[j] = av; ++ia; }
            else          { m[j] = bv; ++ib; }
        }
        int row = tid >> 1;
        float* outp = g_cand + ((size_t)(m0 + row) * NSPLIT + blockIdx.y) * K_TOP;
#pragma unroll
        for (int j = 0; j < K_TOP; ++j) outp[j] = m[j];
    }
}

// ---------------- final merge + weights ----------------
__global__ __launch_bounds__(32) void merge_kernel(float* __restrict__ out) {
    int qy = blockIdx.x;
    int s = threadIdx.x;   // 0..31 = split id
    __shared__ float sm[NSPLIT * K_TOP];
    const float* cp = g_cand + ((size_t)qy * NSPLIT + s) * K_TOP;
#pragma unroll
    for (int j = 0; j < K_TOP; ++j) sm[s * K_TOP + j] = cp[j];
    __syncwarp();

    for (int half = NSPLIT / 2; half >= 1; half >>= 1) {
        if (s < half) {
            float* a = &sm[s * K_TOP];
            float* b = &sm[(s + half) * K_TOP];
            float m[K_TOP];
            int ia = 0, ib = 0;
#pragma unroll
            for (int j = 0; j < K_TOP; ++j) {
                float av = a[ia], bv = b[ib];
                if (av >= bv) { m[j] = av; ++ia; }
                else          { m[j] = bv; ++ib; }
            }
#pragma unroll
            for (int j = 0; j < K_TOP; ++j) a[j] = m[j];
        }
        __syncwarp();
    }

    if (s == 0) {
        float w[K_TOP];
        float ssum = 0.f;
#pragma unroll
        for (int j = 0; j < K_TOP; ++j) {
            float d2 = fmaxf(2.0f - 2.0f * sm[j], 1e-12f);
            w[j] = expf(-sqrtf(d2));
            ssum += w[j];
        }
        float inv = 1.0f / fmaxf(ssum, 1e-12f);
#pragma unroll
        for (int j = 0; j < K_TOP; ++j)
            out[(size_t)qy * K_TOP + j] = w[j] * inv;
    }
}

// ---------------- launch ----------------
extern "C" void kernel_launch(void* const* d_in, const int* in_sizes, int n_in,
                              void* d_out, int out_size) {
    const float* x    = (const float*)d_in[0];
    const float* refs = (const float*)d_in[1];
    float* out = (float*)d_out;

    static bool attr_set = false;
    if (!attr_set) {
        cudaFuncSetAttribute(fused_gemm_topk_kernel,
                             cudaFuncAttributeMaxDynamicSharedMemorySize, SMEM_TOTAL);
        attr_set = true;
    }

    prep_x_kernel<<<N_Q, 128>>>(x);
    conv_refs_kernel<<<16384, 256>>>(refs);
    fused_gemm_topk_kernel<<<dim3(N_Q / BM, NSPLIT), 256, SMEM_TOTAL>>>();
    merge_kernel<<<N_Q, 32>>>(out);
}

// round 4
// speedup vs baseline: 1.4896x; 1.0869x over previous
#include <cuda_runtime.h>
#include <cuda_bf16.h>
#include <cstdint>

#define N_Q    4096
#define N_R    65536
#define DIM    512
#define K_TOP  16

#define BM     128
#define BN     128
#define BK     32
#define NSPLIT 32
#define CHUNK  (N_R / NSPLIT)   // 2048
#define NT     (CHUNK / BN)     // 16
#define NKT    (DIM / BK)       // 16
#define TOT    (NT * NKT)       // 256

#define APITCH    80            // bytes per smem row (64 data + 16 pad)
#define STG_BYTES (BM * APITCH) // 10240
#define AS_OFF    0
#define BS_OFF    (2 * STG_BYTES)
#define SC_OFF    (4 * STG_BYTES)
#define SPITCH    130
#define SMEM_TOTAL (SC_OFF + BM * SPITCH * 4)   // 107520

// ---------------- scratch ----------------
__device__ __nv_bfloat16 g_xb[(size_t)N_Q * DIM];              // 4 MB
__device__ __nv_bfloat16 g_rb[(size_t)N_R * DIM];              // 64 MB
__device__ float         g_cand[(size_t)N_Q * NSPLIT * K_TOP]; // 8 MB

// ---------------- helpers ----------------
__device__ __forceinline__ uint32_t smem_u32(const void* p) {
    uint32_t a;
    asm("{ .reg .u64 t; cvta.to.shared.u64 t, %1; cvt.u32.u64 %0, t; }" : "=r"(a) : "l"(p));
    return a;
}
__device__ __forceinline__ void cp_async16(uint32_t dst, const void* src) {
    asm volatile("cp.async.cg.shared.global [%0], [%1], 16;\n" :: "r"(dst), "l"(src));
}
__device__ __forceinline__ void cp_commit() { asm volatile("cp.async.commit_group;\n" ::: "memory"); }
__device__ __forceinline__ void cp_wait_all() { asm volatile("cp.async.wait_group 0;\n" ::: "memory"); }

__device__ __forceinline__ void mma_bf16(float* c, const uint32_t* a, const uint32_t* b) {
    asm volatile(
        "mma.sync.aligned.m16n8k16.row.col.f32.bf16.bf16.f32 "
        "{%0,%1,%2,%3}, {%4,%5,%6,%7}, {%8,%9}, {%0,%1,%2,%3};\n"
        : "+f"(c[0]), "+f"(c[1]), "+f"(c[2]), "+f"(c[3])
        : "r"(a[0]), "r"(a[1]), "r"(a[2]), "r"(a[3]),
          "r"(b[0]), "r"(b[1]));
}
#define LDSM4(r0, r1, r2, r3, addr) \
    asm volatile("ldmatrix.sync.aligned.m8n8.x4.shared.b16 {%0,%1,%2,%3}, [%4];" \
                 : "=r"(r0), "=r"(r1), "=r"(r2), "=r"(r3) : "r"(addr))

// ---------------- prep: normalize x -> bf16 ----------------
__global__ void prep_x_kernel(const float* __restrict__ x) {
    int row = blockIdx.x;
    int t = threadIdx.x;
    const float* xr = x + (size_t)row * DIM;
    float v[4];
    float ss = 0.f;
#pragma unroll
    for (int i = 0; i < 4; ++i) { v[i] = xr[i * 128 + t]; ss += v[i] * v[i]; }
#pragma unroll
    for (int o = 16; o > 0; o >>= 1) ss += __shfl_xor_sync(0xffffffffu, ss, o);
    __shared__ float red[4];
    if ((t & 31) == 0) red[t >> 5] = ss;
    __syncthreads();
    float tot = red[0] + red[1] + red[2] + red[3];
    float scale = 1.0f / fmaxf(sqrtf(tot), 1e-12f);
#pragma unroll
    for (int i = 0; i < 4; ++i)
        g_xb[(size_t)row * DIM + i * 128 + t] = __float2bfloat16(v[i] * scale);
}

// ---------------- prep: refs fp32 -> bf16 ----------------
__global__ void conv_refs_kernel(const float* __restrict__ r) {
    size_t total4 = (size_t)N_R * DIM / 4;
    const float4* r4 = (const float4*)r;
    __nv_bfloat162* out2 = (__nv_bfloat162*)g_rb;
    for (size_t i = (size_t)blockIdx.x * blockDim.x + threadIdx.x; i < total4;
         i += (size_t)gridDim.x * blockDim.x) {
        float4 f = r4[i];
        out2[i * 2]     = __floats2bfloat162_rn(f.x, f.y);
        out2[i * 2 + 1] = __floats2bfloat162_rn(f.z, f.w);
    }
}

// ---------------- stage loader: A[128][32] + B[128][32] bf16, 16B chunks ----
__device__ __forceinline__ void issue_stage(uint32_t sb, int buf, int j,
                                            const __nv_bfloat16* Ag,
                                            const __nv_bfloat16* Bg, int tid) {
    int nt = j >> 4;
    int kof = (j & 15) * BK;
    uint32_t abase = sb + AS_OFF + buf * STG_BYTES;
    uint32_t bbase = sb + BS_OFF + buf * STG_BYTES;
    const __nv_bfloat16* Bt = Bg + (size_t)nt * BN * DIM;
#pragma unroll
    for (int h = 0; h < 2; ++h) {
        int ch = tid + h * 256;     // 0..511
        int row = ch >> 2;
        int c = ch & 3;
        cp_async16(abase + row * APITCH + c * 16,
                   Ag + (size_t)row * DIM + kof + c * 8);
        cp_async16(bbase + row * APITCH + c * 16,
                   Bt + (size_t)row * DIM + kof + c * 8);
    }
}

// ---------------- fused GEMM (ldmatrix + mma.sync) + top-16 ----------------
__global__ __launch_bounds__(256, 2) void fused_gemm_topk_kernel() {
    extern __shared__ uint8_t smem[];
    uint32_t sb = smem_u32(smem);
    float* sc = (float*)(smem + SC_OFF);

    int tid = threadIdx.x;
    int lane = tid & 31, warp = tid >> 5;
    int m0 = blockIdx.x * BM;
    int n0 = blockIdx.y * CHUNK;
    const __nv_bfloat16* Ag = g_xb + (size_t)m0 * DIM;
    const __nv_bfloat16* Bg = g_rb + (size_t)n0 * DIM;

    int wm = (warp >> 2) * 64;
    int wn = (warp & 3) * 32;
    int g = lane >> 2, q = lane & 3;

    // ldmatrix per-lane offsets
    uint32_t aoff = (uint32_t)((lane & 15) * APITCH + (lane >> 4) * 16);
    uint32_t boff = (uint32_t)((((lane >> 4) * 8) + (lane & 7)) * APITCH +
                               ((lane >> 3) & 1) * 16);

    float t16[K_TOP];
#pragma unroll
    for (int j = 0; j < K_TOP; ++j) t16[j] = -1e30f;

    float acc[16][4];
#pragma unroll
    for (int i = 0; i < 16; ++i)
#pragma unroll
        for (int j = 0; j < 4; ++j) acc[i][j] = 0.f;

    // prologue
    issue_stage(sb, 0, 0, Ag, Bg, tid);
    cp_commit();

    int it = 0;
    for (int nt = 0; nt < NT; ++nt) {
        for (int kt = 0; kt < NKT; ++kt) {
            cp_wait_all();
            __syncthreads();
            if (it + 1 < TOT) {
                issue_stage(sb, (it + 1) & 1, it + 1, Ag, Bg, tid);
                cp_commit();
            }
            int buf = it & 1;
            uint32_t abase = sb + AS_OFF + buf * STG_BYTES;
            uint32_t bbase = sb + BS_OFF + buf * STG_BYTES;
#pragma unroll
            for (int kk = 0; kk < 2; ++kk) {
                uint32_t af[4][4], bf2[4][2];
#pragma unroll
                for (int mf = 0; mf < 4; ++mf) {
                    uint32_t ad = abase + (wm + mf * 16) * APITCH + kk * 32 + aoff;
                    LDSM4(af[mf][0], af[mf][1], af[mf][2], af[mf][3], ad);
                }
#pragma unroll
                for (int pr = 0; pr < 2; ++pr) {
                    uint32_t bd = bbase + (wn + pr * 16) * APITCH + kk * 32 + boff;
                    LDSM4(bf2[pr * 2][0], bf2[pr * 2][1],
                          bf2[pr * 2 + 1][0], bf2[pr * 2 + 1][1], bd);
                }
#pragma unroll
                for (int mf = 0; mf < 4; ++mf)
#pragma unroll
                    for (int nf = 0; nf < 4; ++nf)
                        mma_bf16(acc[mf * 4 + nf], af[mf], bf2[nf]);
            }
            ++it;
        }

        // epilogue: spill tile to smem scores
        __syncthreads();
#pragma unroll
        for (int mf = 0; mf < 4; ++mf) {
#pragma unroll
            for (int nf = 0; nf < 4; ++nf) {
                int r0 = wm + mf * 16 + g;
                int c0 = wn + nf * 8 + q * 2;
                sc[r0 * SPITCH + c0]           = acc[mf * 4 + nf][0];
                sc[r0 * SPITCH + c0 + 1]       = acc[mf * 4 + nf][1];
                sc[(r0 + 8) * SPITCH + c0]     = acc[mf * 4 + nf][2];
                sc[(r0 + 8) * SPITCH + c0 + 1] = acc[mf * 4 + nf][3];
                acc[mf * 4 + nf][0] = 0.f; acc[mf * 4 + nf][1] = 0.f;
                acc[mf * 4 + nf][2] = 0.f; acc[mf * 4 + nf][3] = 0.f;
            }
        }
        __syncthreads();

        // top-k scan: thread owns (row tid>>1, cols (tid&1)*64 .. +63)
        {
            const float* rowp = sc + (tid >> 1) * SPITCH + (tid & 1) * 64;
            float th = t16[K_TOP - 1];
#pragma unroll 8
            for (int j = 0; j < 64; ++j) {
                float v = rowp[j];
                if (v > th) {
                    t16[K_TOP - 1] = v;
#pragma unroll
                    for (int p = K_TOP - 1; p > 0; --p) {
                        float a = t16[p - 1], bb = t16[p];
                        t16[p - 1] = fmaxf(a, bb);
                        t16[p]     = fminf(a, bb);
                    }
                    th = t16[K_TOP - 1];
                }
            }
        }
        __syncthreads();
    }

    // pair-merge col-halves, write candidates
    float* lists = sc;
#pragma unroll
    for (int j = 0; j < K_TOP; ++j) lists[tid * K_TOP + j] = t16[j];
    __syncthreads();

    if ((tid & 1) == 0) {
        const float* a = &lists[tid * K_TOP];
        const float* b = &lists[(tid + 1) * K_TOP];
        float m[K_TOP];
        int ia = 0, ib = 0;
#pragma unroll
        for (int j = 0; j < K_TOP; ++j) {
            float av = a[ia], bv = b[ib];
            if (av >= bv) { m[j] = av; ++ia; }
            else          { m[j] = bv; ++ib; }
        }
        int row = tid >> 1;
        float* outp = g_cand + ((size_t)(m0 + row) * NSPLIT + blockIdx.y) * K_TOP;
#pragma unroll
        for (int j = 0; j < K_TOP; ++j) outp[j] = m[j];
    }
}

// ---------------- final merge + weights ----------------
__global__ __launch_bounds__(32) void merge_kernel(float* __restrict__ out) {
    int qy = blockIdx.x;
    int s = threadIdx.x;
    __shared__ float sm[NSPLIT * K_TOP];
    const float* cp = g_cand + ((size_t)qy * NSPLIT + s) * K_TOP;
#pragma unroll
    for (int j = 0; j < K_TOP; ++j) sm[s * K_TOP + j] = cp[j];
    __syncwarp();

    for (int half = NSPLIT / 2; half >= 1; half >>= 1) {
        if (s < half) {
            float* a = &sm[s * K_TOP];
            float* b = &sm[(s + half) * K_TOP];
            float m[K_TOP];
            int ia = 0, ib = 0;
#pragma unroll
            for (int j = 0; j < K_TOP; ++j) {
                float av = a[ia], bv = b[ib];
                if (av >= bv) { m[j] = av; ++ia; }
                else          { m[j] = bv; ++ib; }
            }
#pragma unroll
            for (int j = 0; j < K_TOP; ++j) a[j] = m[j];
        }
        __syncwarp();
    }

    if (s == 0) {
        float w[K_TOP];
        float ssum = 0.f;
#pragma unroll
        for (int j = 0; j < K_TOP; ++j) {
            float d2 = fmaxf(2.0f - 2.0f * sm[j], 1e-12f);
            w[j] = expf(-sqrtf(d2));
            ssum += w[j];
        }
        float inv = 1.0f / fmaxf(ssum, 1e-12f);
#pragma unroll
        for (int j = 0; j < K_TOP; ++j)
            out[(size_t)qy * K_TOP + j] = w[j] * inv;
    }
}

// ---------------- launch ----------------
extern "C" void kernel_launch(void* const* d_in, const int* in_sizes, int n_in,
                              void* d_out, int out_size) {
    const float* x    = (const float*)d_in[0];
    const float* refs = (const float*)d_in[1];
    float* out = (float*)d_out;

    static bool attr_set = false;
    if (!attr_set) {
        cudaFuncSetAttribute(fused_gemm_topk_kernel,
                             cudaFuncAttributeMaxDynamicSharedMemorySize, SMEM_TOTAL);
        attr_set = true;
    }

    prep_x_kernel<<<N_Q, 128>>>(x);
    conv_refs_kernel<<<16384, 256>>>(refs);
    fused_gemm_topk_kernel<<<dim3(N_Q / BM, NSPLIT), 256, SMEM_TOTAL>>>();
    merge_kernel<<<N_Q, 32>>>(out);
}